// round 3
// baseline (speedup 1.0000x reference)
#include <cuda_runtime.h>
#include <math.h>

#define Bb   256
#define Ll   512
#define Ff   28
#define Hh   512
#define G4   2048
#define NBLK 128
#define NTHR 256

// ---------------- scratch ----------------
__device__ float g_xf[Ll * Bb * Ff];      // [l][b][f]
__device__ float g_ua[Ll * Bb];           // [l][b]
__device__ float g_bm[Ll * Bb];           // [l][b]
__device__ float g_uab[Bb * Ll];          // [b][l]
__device__ float g_bmb[Bb * Ll];          // [b][l]
__device__ float g_h[Bb * Hh];
__device__ float g_c[Bb * Hh];
__device__ float g_wapart[Bb * 32];       // [b][ntile]
__device__ float g_fcpart[Ll * Bb * 32];  // [t][b][ntile]
__device__ float g_stats[Ll * 2];         // [l]{m, 1/D}
__device__ float g_ctx[Bb * Ff];          // [b][f]
__device__ float g_wpack[G4 * Hh];
__device__ unsigned g_cnt = 0;
__device__ volatile unsigned g_gen = 0;

__device__ __forceinline__ void grid_barrier() {
    __syncthreads();
    if (threadIdx.x == 0) {
        __threadfence();
        unsigned gen = g_gen;
        if (atomicAdd(&g_cnt, 1u) == NBLK - 1) {
            g_cnt = 0;
            __threadfence();
            g_gen = gen + 1;
        } else {
            while (g_gen == gen) { __nanosleep(20); }
            __threadfence();
        }
    }
    __syncthreads();
}

__device__ __forceinline__ float sigm(float x) { return 1.f / (1.f + __expf(-x)); }

// wpack[((nt*512 + k)*16 + nri)*4 + q] = W_hh[(q*512 + nt*16 + nri)*512 + k]
__global__ void pack_whh(const float* __restrict__ whh) {
    int o = blockIdx.x * blockDim.x + threadIdx.x;
    if (o >= G4 * Hh) return;
    int q = o & 3, nri = (o >> 2) & 15, k = (o >> 6) & 511, nt = o >> 15;
    g_wpack[o] = whh[(q * Hh + nt * 16 + nri) * Hh + k];
}

__global__ void prep(const float* __restrict__ x, const float* __restrict__ mask,
                     const float* __restrict__ w1, const float* __restrict__ b1,
                     const float* __restrict__ cw, const float* __restrict__ cb) {
    __shared__ float w1s[Ff * Ff * 3];
    __shared__ float cws[Ff];
    for (int i = threadIdx.x; i < Ff * Ff * 3; i += blockDim.x) w1s[i] = w1[i];
    if (threadIdx.x < Ff) cws[threadIdx.x] = cw[threadIdx.x];
    __syncthreads();
    int gid = blockIdx.x * blockDim.x + threadIdx.x;
    int b = gid / Ll, l = gid % Ll;
    float m = mask[b * Ll + l];
    const float* xrow = x + (size_t)(b * Ll + l) * Ff;
    float accu = 0.f;
    for (int fo = 0; fo < Ff; fo++) {
        float a = b1[fo];
        #pragma unroll
        for (int k = 0; k < 3; k++) {
            int ll = l - 1 + k;
            if (ll >= 0 && ll < Ll) {
                const float* xp = x + (size_t)(b * Ll + ll) * Ff;
                const float* wp = w1s + fo * (Ff * 3) + k;
                #pragma unroll 7
                for (int fi = 0; fi < Ff; fi++) a += xp[fi] * wp[fi * 3];
            }
        }
        a *= m;
        a = (a > 0.f) ? a : (expf(a) - 1.f);   // elu
        float xfv = a + xrow[fo];
        g_xf[(l * Bb + b) * Ff + fo] = xfv;
        accu += xfv * cws[fo];
    }
    float ua = accu + cb[0];
    float bm = 1e9f * (m - 1.f);
    g_ua[l * Bb + b] = ua;  g_uab[b * Ll + l] = ua;
    g_bm[l * Bb + b] = bm;  g_bmb[b * Ll + l] = bm;
}

__device__ __forceinline__ void gemm_chunk(int kc0, int b0, int nt, int tid, int tx, int ty,
                                           float (&acc)[4][4], float* hs, float* ws) {
    __syncthreads();
    #pragma unroll
    for (int r = 0; r < 2; r++) {
        int i4 = tid + r * NTHR;
        int bb = i4 >> 3, c4 = i4 & 7;
        *(float4*)&hs[bb * 36 + c4 * 4] =
            *(const float4*)&g_h[(b0 + bb) * Hh + kc0 + c4 * 4];
        *(float4*)&ws[i4 * 4] =
            *(const float4*)&g_wpack[(nt * Hh + kc0) * 64 + i4 * 4];
    }
    __syncthreads();
    #pragma unroll
    for (int k = 0; k < 32; k++) {
        float4 wv = *(float4*)&ws[k * 64 + tx * 4];
        float h0 = hs[(ty * 4 + 0) * 36 + k];
        float h1 = hs[(ty * 4 + 1) * 36 + k];
        float h2 = hs[(ty * 4 + 2) * 36 + k];
        float h3 = hs[(ty * 4 + 3) * 36 + k];
        acc[0][0] += h0 * wv.x; acc[0][1] += h0 * wv.y; acc[0][2] += h0 * wv.z; acc[0][3] += h0 * wv.w;
        acc[1][0] += h1 * wv.x; acc[1][1] += h1 * wv.y; acc[1][2] += h1 * wv.z; acc[1][3] += h1 * wv.w;
        acc[2][0] += h2 * wv.x; acc[2][1] += h2 * wv.y; acc[2][2] += h2 * wv.z; acc[2][3] += h2 * wv.w;
        acc[3][0] += h3 * wv.x; acc[3][1] += h3 * wv.y; acc[3][2] += h3 * wv.z; acc[3][3] += h3 * wv.w;
    }
}

__global__ void __launch_bounds__(NTHR, 1) scan(
    const float* __restrict__ fc1w, const float* __restrict__ fc1b,
    const float* __restrict__ wih,  const float* __restrict__ bih,
    const float* __restrict__ bhh,  const float* __restrict__ w2) {

    __shared__ __align__(16) float hs[64 * 36];
    __shared__ __align__(16) float ws[32 * 64];
    __shared__ float wa_s[Bb];
    __shared__ float red[64 * 16];
    __shared__ float ctx_s[64 * Ff];
    __shared__ float wih_s[64 * 29];   // [(q*16+tx)*29 + f]
    __shared__ float bsum_s[64];       // [q*16+tx]
    __shared__ float ctxacc[2 * 4 * Ff];
    __shared__ float stm[8], stdd[8];

    const int tid = threadIdx.x;
    const int blk = blockIdx.x;
    const int bt = blk >> 5, nt = blk & 31;
    const int b0 = bt * 64, n0 = nt * 16;
    const int tx = tid & 15, ty = tid >> 4;
    const int n = n0 + tx;

    const float f1n = fc1w[n];
    const float w2n = w2[n];
    const float f1b0 = fc1b[0];

    for (int i = tid; i < 64 * Ff; i += NTHR) {
        int r = i / Ff, f = i % Ff;          // r = q*16 + txr
        int row = (r >> 4) * Hh + n0 + (r & 15);
        wih_s[r * 29 + f] = wih[row * Ff + f];
    }
    if (tid < 64) {
        int row = (tid >> 4) * Hh + n0 + (tid & 15);
        bsum_s[tid] = bih[row] + bhh[row];
    }

    for (int i = blk * NTHR + tid; i < Bb * Hh; i += NBLK * NTHR) { g_h[i] = 0.f; g_c[i] = 0.f; }
    for (int i = blk * NTHR + tid; i < Bb * 32; i += NBLK * NTHR) g_wapart[i] = 0.f;
    grid_barrier();

    float acc[4][4];
    #pragma unroll
    for (int i = 0; i < 4; i++)
        #pragma unroll
        for (int j = 0; j < 4; j++) acc[i][j] = 0.f;

    for (int t = 0; t < Ll; t++) {
        // ---- PHASE A: w_a reduce + softmax stats + GEMM 0-7 ----
        {
            float s = 0.f;
            const float* wp = g_wapart + tid * 32;
            #pragma unroll
            for (int j = 0; j < 32; j++) s += wp[j];
            wa_s[tid] = s + f1b0;
        }
        __syncthreads();
        {
            int lq = tid >> 6, tsub = tid & 63;
            int l = blk * 4 + lq;
            float mx = -1e30f, dd = 0.f;
            #pragma unroll
            for (int r = 0; r < 4; r++) {
                int b = tsub + r * 64;
                float s = g_ua[l * Bb + b] + wa_s[b];
                s = (s > 0.f) ? s : 0.01f * s;
                s += g_bm[l * Bb + b];
                float mn = fmaxf(mx, s);
                dd = dd * __expf(mx - mn) + __expf(s - mn);
                mx = mn;
            }
            #pragma unroll
            for (int off = 16; off; off >>= 1) {
                float mo = __shfl_down_sync(0xffffffffu, mx, off);
                float d2 = __shfl_down_sync(0xffffffffu, dd, off);
                float mn = fmaxf(mx, mo);
                dd = dd * __expf(mx - mn) + d2 * __expf(mo - mn);
                mx = mn;
            }
            if ((tid & 31) == 0) { stm[tid >> 5] = mx; stdd[tid >> 5] = dd; }
        }
        __syncthreads();
        if (tid < 4) {
            float m1 = stm[tid * 2], d1 = stdd[tid * 2];
            float m2 = stm[tid * 2 + 1], d2 = stdd[tid * 2 + 1];
            float mn = fmaxf(m1, m2);
            float dd = d1 * __expf(m1 - mn) + d2 * __expf(m2 - mn);
            int l = blk * 4 + tid;
            g_stats[l * 2] = mn;
            g_stats[l * 2 + 1] = 1.f / dd;
        }
        for (int ch = 0; ch < 8; ch++) gemm_chunk(ch * 32, b0, nt, tid, tx, ty, acc, hs, ws);
        grid_barrier();

        // ---- PHASE B: context + GEMM 8-15 ----
        {
            int w = tid >> 5, lane = tid & 31;
            int bloc = w >> 2, q4 = w & 3;
            int b = blk * 2 + bloc;
            float wab = wa_s[b];
            float accf = 0.f;
            for (int lg = q4 * 128; lg < q4 * 128 + 128; lg += 32) {
                int lme = lg + lane;
                float su = g_uab[b * Ll + lme] + wab;
                su = (su > 0.f) ? su : 0.01f * su;
                su += g_bmb[b * Ll + lme];
                float p = __expf(su - g_stats[lme * 2]) * g_stats[lme * 2 + 1];
                #pragma unroll
                for (int j = 0; j < 32; j++) {
                    float pj = __shfl_sync(0xffffffffu, p, j);
                    if (lane < Ff)
                        accf += pj * g_xf[((lg + j) * Bb + b) * Ff + lane];
                }
            }
            if (lane < Ff) ctxacc[(bloc * 4 + q4) * Ff + lane] = accf;
        }
        __syncthreads();
        if (tid < 2 * Ff) {
            int bloc = tid / Ff, f = tid % Ff;
            float s = 0.f;
            #pragma unroll
            for (int q4 = 0; q4 < 4; q4++) s += ctxacc[(bloc * 4 + q4) * Ff + f];
            g_ctx[(blk * 2 + bloc) * Ff + f] = s;
        }
        for (int ch = 8; ch < 16; ch++) gemm_chunk(ch * 32, b0, nt, tid, tx, ty, acc, hs, ws);
        grid_barrier();

        // ---- PHASE C: epilogue + LSTM pointwise ----
        for (int i = tid; i < 64 * Ff; i += NTHR) ctx_s[i] = g_ctx[b0 * Ff + i];
        __syncthreads();
        float hnv[4];
        #pragma unroll
        for (int bi = 0; bi < 4; bi++) {
            int bl = ty * 4 + bi;
            const float* cp = ctx_s + bl * Ff;
            float d0 = 0.f, d1 = 0.f, d2 = 0.f, d3 = 0.f;
            #pragma unroll
            for (int fI = 0; fI < Ff; fI++) {
                float cv = cp[fI];
                d0 += cv * wih_s[(0 * 16 + tx) * 29 + fI];
                d1 += cv * wih_s[(1 * 16 + tx) * 29 + fI];
                d2 += cv * wih_s[(2 * 16 + tx) * 29 + fI];
                d3 += cv * wih_s[(3 * 16 + tx) * 29 + fI];
            }
            float gi = acc[bi][0] + d0 + bsum_s[0 * 16 + tx];
            float gf = acc[bi][1] + d1 + bsum_s[1 * 16 + tx];
            float gg = acc[bi][2] + d2 + bsum_s[2 * 16 + tx];
            float go = acc[bi][3] + d3 + bsum_s[3 * 16 + tx];
            int bg = b0 + bl;
            float co = g_c[bg * Hh + n];
            float cn = sigm(gf) * co + sigm(gi) * tanhf(gg);
            float hn = sigm(go) * tanhf(cn);
            g_c[bg * Hh + n] = cn;
            g_h[bg * Hh + n] = hn;
            hnv[bi] = hn;
            acc[bi][0] = acc[bi][1] = acc[bi][2] = acc[bi][3] = 0.f;
        }
        #pragma unroll
        for (int bi = 0; bi < 4; bi++) red[(ty * 4 + bi) * 16 + tx] = hnv[bi] * f1n;
        __syncthreads();
        if (tid < 64) {
            float s = 0.f;
            #pragma unroll
            for (int j = 0; j < 16; j++) s += red[tid * 16 + j];
            g_wapart[(b0 + tid) * 32 + nt] = s;
        }
        __syncthreads();
        #pragma unroll
        for (int bi = 0; bi < 4; bi++) red[(ty * 4 + bi) * 16 + tx] = hnv[bi] * w2n;
        __syncthreads();
        if (tid < 64) {
            float s = 0.f;
            #pragma unroll
            for (int j = 0; j < 16; j++) s += red[tid * 16 + j];
            g_fcpart[(t * Bb + b0 + tid) * 32 + nt] = s;
        }
        grid_barrier();
    }
}

__global__ void final_out(const float* __restrict__ x, const float* __restrict__ mask,
                          const float* __restrict__ w2, const float* __restrict__ b2,
                          float* __restrict__ out) {
    __shared__ float w2s[Ff];
    if (threadIdx.x < Ff) w2s[threadIdx.x] = w2[Hh + threadIdx.x];
    __syncthreads();
    int gid = blockIdx.x * blockDim.x + threadIdx.x;
    int b = gid / Ll, l = gid % Ll;
    const float* fp = g_fcpart + (size_t)(l * Bb + b) * 32;
    float s = 0.f;
    #pragma unroll
    for (int j = 0; j < 32; j++) s += fp[j];
    float m = mask[b * Ll + l];
    s *= m;
    const float* xr = x + (size_t)(b * Ll + l) * Ff;
    #pragma unroll 7
    for (int f = 0; f < Ff; f++) s += xr[f] * w2s[f];
    out[b * Ll + l] = (s + b2[0]) * m;
}

extern "C" void kernel_launch(void* const* d_in, const int* in_sizes, int n_in,
                              void* d_out, int out_size) {
    const float* x      = (const float*)d_in[0];
    const float* mask   = (const float*)d_in[1];
    const float* conv1w = (const float*)d_in[2];
    const float* conv1b = (const float*)d_in[3];
    const float* convw  = (const float*)d_in[4];
    const float* convb  = (const float*)d_in[5];
    const float* conv2w = (const float*)d_in[6];
    const float* conv2b = (const float*)d_in[7];
    const float* wih    = (const float*)d_in[8];
    const float* whh    = (const float*)d_in[9];
    const float* bih    = (const float*)d_in[10];
    const float* bhh    = (const float*)d_in[11];
    const float* fc1w   = (const float*)d_in[12];
    const float* fc1b   = (const float*)d_in[13];
    float* out = (float*)d_out;

    pack_whh<<<(G4 * Hh + 255) / 256, 256>>>(whh);
    prep<<<(Bb * Ll) / 256, 256>>>(x, mask, conv1w, conv1b, convw, convb);
    scan<<<NBLK, NTHR>>>(fc1w, fc1b, wih, bih, bhh, conv2w);
    final_out<<<(Bb * Ll) / 256, 256>>>(x, mask, conv2w, conv2b, out);
}

// round 6
// speedup vs baseline: 1.7169x; 1.7169x over previous
#include <cuda_runtime.h>
#include <cuda_bf16.h>
#include <math.h>
#include <stdint.h>

typedef unsigned short ush;

#define Bb 256
#define Ll 512
#define Ff 28
#define NBLK 128
#define NTHR 256

#define BSTRIDE 552          // 544 + 8 pad (bf16 elems)
#define ASTRIDE 136          // 128 + 8 pad
#define BBYTES  (2*64*BSTRIDE*2)   // 141312 per nt (hi+lo)
#define ACHB    (2*64*ASTRIDE*2)   // 34816 per chunk (hi+lo)

#define OFF_B    0
#define OFF_A    141312
#define OFF_G    210944
#define OFF_WAS  228352
#define OFF_BSUM 229376
#define OFF_CTXA 229632
#define OFF_STM  230528
#define SMEM_SZ  230592

__device__ __align__(16) ush g_wb[32*2*64*BSTRIDE];        // [nt][half][n64][552]
__device__ __align__(16) ush g_ab[4*5*2*64*ASTRIDE];       // [mt][chunk5][half][row64][136]
__device__ float g_xf[Ll*Bb*Ff];
__device__ float g_ua[Ll*Bb];
__device__ float g_bm[Ll*Bb];
__device__ float g_uab[Bb*Ll];
__device__ float g_bmb[Bb*Ll];
__device__ float g_wapart[Bb*32];
__device__ float g_fcpart[(size_t)Ll*Bb*32];
__device__ float g_stats[Ll*2];
__device__ unsigned g_cnt=0;
__device__ volatile unsigned g_gen=0;

__device__ __forceinline__ void grid_barrier(){
    __syncthreads();
    if(threadIdx.x==0){
        __threadfence();
        unsigned gen=g_gen;
        if(atomicAdd(&g_cnt,1u)==NBLK-1){ g_cnt=0; __threadfence(); g_gen=gen+1; }
        else { while(g_gen==gen){ __nanosleep(20);} __threadfence(); }
    }
    __syncthreads();
}
__device__ __forceinline__ float sigm(float x){ return 1.f/(1.f+__expf(-x)); }
__device__ __forceinline__ int pos4(int km){ return 4*((km&7)>>1)+(km&1)+2*(km>>3); }
__device__ __forceinline__ uint32_t smem_u32(const void* p){
    uint32_t a; asm("{ .reg .u64 t; cvta.to.shared.u64 t, %1; cvt.u32.u64 %0, t; }":"=r"(a):"l"(p)); return a;
}
__device__ __forceinline__ void cpa16(uint32_t s, const void* g){
    asm volatile("cp.async.cg.shared.global [%0], [%1], 16;" :: "r"(s), "l"(g));
}
#define CP_COMMIT() asm volatile("cp.async.commit_group;":::"memory")
#define CP_WAIT(n)  asm volatile("cp.async.wait_group %0;"::"n"(n):"memory")

#define MMA(Cr,A0,A1,A2,A3,B0,B1) \
  asm volatile("mma.sync.aligned.m16n8k16.row.col.f32.bf16.bf16.f32 " \
    "{%0,%1,%2,%3},{%4,%5,%6,%7},{%8,%9},{%0,%1,%2,%3};" \
    : "+f"(Cr[0]),"+f"(Cr[1]),"+f"(Cr[2]),"+f"(Cr[3]) \
    : "r"(A0),"r"(A1),"r"(A2),"r"(A3),"r"(B0),"r"(B1))

__device__ __forceinline__ void bf16split(float v, ush& hi, ush& lo){
    __nv_bfloat16 h=__float2bfloat16(v);
    __nv_bfloat16 l=__float2bfloat16(v-__bfloat162float(h));
    hi=*(ush*)&h; lo=*(ush*)&l;
}

__device__ __forceinline__ void mma_chunk(const ush* smA, const ush* smB,
        int bK, int ktn, int mi, int nig, int lane, float (&C)[4][4]){
    const int r=lane>>2, c4=lane&3;
    const ush* aH = smA + (mi*16+r)*ASTRIDE + c4*4;
    const ush* aL = aH + 64*ASTRIDE;
    const ush* bB = smB + (nig*32+r)*BSTRIDE + bK + c4*4;
    for(int kt=0; kt<ktn; kt++){
        int ka=kt*16;
        uint2 a0=*(const uint2*)(aH+ka);
        uint2 a1=*(const uint2*)(aH+8*ASTRIDE+ka);
        uint2 l0=*(const uint2*)(aL+ka);
        uint2 l1=*(const uint2*)(aL+8*ASTRIDE+ka);
        #pragma unroll
        for(int ni=0; ni<4; ni++){
            const ush* bp = bB + ni*8*BSTRIDE + ka;
            uint2 bh=*(const uint2*)bp;
            uint2 bl=*(const uint2*)(bp+64*BSTRIDE);
            MMA(C[ni], a0.x,a1.x,a0.y,a1.y, bh.x,bh.y);
            MMA(C[ni], a0.x,a1.x,a0.y,a1.y, bl.x,bl.y);
            MMA(C[ni], l0.x,l1.x,l0.y,l1.y, bh.x,bh.y);
        }
    }
}

// ---- pack W (Whh cols 0..511, Wih cols 512..539, zero pad to 543) ----
__global__ void pack_w(const float* __restrict__ whh, const float* __restrict__ wih){
    int o=blockIdx.x*blockDim.x+threadIdx.x;
    if(o>=32*64*544) return;
    int nt=o/(64*544); int rem=o-nt*64*544; int j=rem/544; int k=rem%544;
    int row=(j&3)*512 + nt*16 + (j>>2);
    float v = (k<512) ? whh[(size_t)row*512+k] : ((k-512<Ff)? wih[row*Ff+(k-512)] : 0.f);
    ush hi,lo; bf16split(v,hi,lo);
    int pos=(k&~15) + pos4(k&15);
    size_t base=(size_t)nt*2*64*BSTRIDE;
    g_wb[base + (size_t)j*BSTRIDE + pos]=hi;
    g_wb[base + (size_t)64*BSTRIDE + (size_t)j*BSTRIDE + pos]=lo;
}
__global__ void zero_ab(){
    int i=blockIdx.x*blockDim.x+threadIdx.x;
    int n=(int)(sizeof(g_ab)/16);
    if(i<n) ((uint4*)g_ab)[i]=make_uint4(0,0,0,0);
}

__global__ void prep(const float* __restrict__ x, const float* __restrict__ mask,
                     const float* __restrict__ w1, const float* __restrict__ b1,
                     const float* __restrict__ cw, const float* __restrict__ cb){
    __shared__ float w1s[Ff*Ff*3];
    __shared__ float cws[Ff];
    for(int i=threadIdx.x;i<Ff*Ff*3;i+=blockDim.x) w1s[i]=w1[i];
    if(threadIdx.x<Ff) cws[threadIdx.x]=cw[threadIdx.x];
    __syncthreads();
    int gid=blockIdx.x*blockDim.x+threadIdx.x;
    int b=gid/Ll, l=gid%Ll;
    float m=mask[b*Ll+l];
    const float* xrow=x+(size_t)(b*Ll+l)*Ff;
    float accu=0.f;
    for(int fo=0;fo<Ff;fo++){
        float a=b1[fo];
        #pragma unroll
        for(int k=0;k<3;k++){
            int ll=l-1+k;
            if(ll>=0&&ll<Ll){
                const float* xp=x+(size_t)(b*Ll+ll)*Ff;
                const float* wp=w1s+fo*(Ff*3)+k;
                #pragma unroll 7
                for(int fi=0;fi<Ff;fi++) a+=xp[fi]*wp[fi*3];
            }
        }
        a*=m;
        a=(a>0.f)?a:(expf(a)-1.f);
        float xfv=a+xrow[fo];
        g_xf[(l*Bb+b)*Ff+fo]=xfv;
        accu+=xfv*cws[fo];
    }
    float ua=accu+cb[0], bm=1e9f*(m-1.f);
    g_ua[l*Bb+b]=ua; g_uab[b*Ll+l]=ua;
    g_bm[l*Bb+b]=bm; g_bmb[b*Ll+l]=bm;
}

__global__ void __launch_bounds__(NTHR,1) scan(
    const float* __restrict__ fc1w, const float* __restrict__ fc1b,
    const float* __restrict__ bih,  const float* __restrict__ bhh,
    const float* __restrict__ w2){

    extern __shared__ __align__(16) char sm[];
    ush*   smB   =(ush*)(sm+OFF_B);
    ush*   smA   =(ush*)(sm+OFF_A);
    float* gates =(float*)(sm+OFF_G);
    float* wa_s  =(float*)(sm+OFF_WAS);
    float* bsum_s=(float*)(sm+OFF_BSUM);
    float* ctxacc=(float*)(sm+OFF_CTXA);
    float* stm   =(float*)(sm+OFF_STM);
    float* stdd  =(float*)(sm+OFF_STM+32);
    const uint32_t saA=smem_u32(sm)+OFF_A;

    const int tid=threadIdx.x, wid=tid>>5, lane=tid&31;
    const int blk=blockIdx.x, mt=blk>>5, nt=blk&31;
    const int mi=wid&3, nig=wid>>2;

    // resident B tile
    { const char* src=(const char*)&g_wb[(size_t)nt*2*64*BSTRIDE];
      uint32_t dB=smem_u32(sm)+OFF_B;
      for(int i=tid;i<BBYTES/16;i+=NTHR) cpa16(dB+i*16, src+(size_t)i*16);
      CP_COMMIT(); CP_WAIT(0); }
    if(tid<64){ int row=(tid&3)*512 + nt*16 + (tid>>2); bsum_s[tid]=bih[row]+bhh[row]; }
    for(int i=blk*NTHR+tid;i<Bb*32;i+=NBLK*NTHR) g_wapart[i]=0.f;

    const int prow=tid>>2, u0=(tid&3)*4;
    float f1v[4],w2v[4],cst[4];
    #pragma unroll
    for(int j=0;j<4;j++){ f1v[j]=fc1w[nt*16+u0+j]; w2v[j]=w2[nt*16+u0+j]; cst[j]=0.f; }
    const float f1b0=fc1b[0];
    const int chh=nt>>3;
    const size_t hHi=(((size_t)(mt*5+chh)*2+0)*64+prow)*ASTRIDE + (nt&7)*16;
    const size_t hLo=hHi + (size_t)64*ASTRIDE;
    __syncthreads();
    grid_barrier();

    for(int t=0;t<Ll;t++){
        // ===== Phase A: wa reduce + batch-softmax stats =====
        { float s=0.f; const float4* wp=(const float4*)(g_wapart+tid*32);
          #pragma unroll
          for(int j2=0;j2<8;j2++){ float4 v=__ldcg(wp+j2); s+=v.x+v.y+v.z+v.w; }
          wa_s[tid]=s+f1b0; }
        __syncthreads();
        { int lq=tid>>6, tsub=tid&63, l=blk*4+lq;
          float mx=-1e30f, dd=0.f;
          #pragma unroll
          for(int r2=0;r2<4;r2++){ int b=tsub+r2*64;
            float s=g_ua[l*Bb+b]+wa_s[b]; s=(s>0.f)?s:0.01f*s; s+=g_bm[l*Bb+b];
            float mn=fmaxf(mx,s); dd=dd*__expf(mx-mn)+__expf(s-mn); mx=mn; }
          #pragma unroll
          for(int o=16;o;o>>=1){ float mo=__shfl_down_sync(0xffffffffu,mx,o),d2=__shfl_down_sync(0xffffffffu,dd,o);
            float mn=fmaxf(mx,mo); dd=dd*__expf(mx-mn)+d2*__expf(mo-mn); mx=mn; }
          if((tid&31)==0){ stm[wid]=mx; stdd[wid]=dd; } }
        __syncthreads();
        if(tid<4){
            float m1=stm[tid*2],d1=stdd[tid*2],m2=stm[tid*2+1],d2=stdd[tid*2+1];
            float mn=fmaxf(m1,m2), dd=d1*__expf(m1-mn)+d2*__expf(m2-mn);
            g_stats[(blk*4+tid)*2]=mn; g_stats[(blk*4+tid)*2+1]=1.f/dd;
        }
        grid_barrier();

        // ===== Phase B: context + h-GEMM (4 chunks) =====
        float C[4][4];
        #pragma unroll
        for(int a=0;a<4;a++){ C[a][0]=0.f;C[a][1]=0.f;C[a][2]=0.f;C[a][3]=0.f; }
        { const char* src=(const char*)&g_ab[(size_t)(mt*5)*2*64*ASTRIDE];
          for(int i=tid;i<ACHB/16;i+=NTHR) cpa16(saA+i*16, src+(size_t)i*16);
          CP_COMMIT(); }
        { int bloc=wid>>2, q4=wid&3, b=blk*2+bloc;
          float wab=wa_s[b], accf=0.f;
          for(int lg=q4*128; lg<q4*128+128; lg+=32){
              int lme=lg+lane;
              float su=g_uab[b*Ll+lme]+wab; su=(su>0.f)?su:0.01f*su; su+=g_bmb[b*Ll+lme];
              float p=__expf(su-__ldcg(&g_stats[lme*2]))*__ldcg(&g_stats[lme*2+1]);
              #pragma unroll
              for(int j2=0;j2<32;j2++){
                  float pj=__shfl_sync(0xffffffffu,p,j2);
                  if(lane<Ff) accf+=pj*g_xf[((lg+j2)*Bb+b)*Ff+lane];
              } }
          if(lane<Ff) ctxacc[(bloc*4+q4)*Ff+lane]=accf; }
        __syncthreads();
        if(tid<2*Ff){
            int bloc=tid/Ff, f=tid-bloc*Ff;
            float s=ctxacc[(bloc*4)*Ff+f]+ctxacc[(bloc*4+1)*Ff+f]+ctxacc[(bloc*4+2)*Ff+f]+ctxacc[(bloc*4+3)*Ff+f];
            int b=blk*2+bloc, mtb=b>>6, rowb=b&63;
            int pos=(f&~15)+pos4(f&15);
            ush hi,lo; bf16split(s,hi,lo);
            size_t base=(((size_t)(mtb*5+4)*2+0)*64+rowb)*ASTRIDE;
            g_ab[base+pos]=hi;
            g_ab[base+(size_t)64*ASTRIDE+pos]=lo;
        }
        for(int c=0;c<4;c++){
            if(c<3){
                const char* s2=(const char*)&g_ab[(size_t)(mt*5+c+1)*2*64*ASTRIDE];
                uint32_t dA=saA+(uint32_t)((c+1)&1)*ACHB;
                for(int i=tid;i<ACHB/16;i+=NTHR) cpa16(dA+i*16, s2+(size_t)i*16);
                CP_COMMIT(); CP_WAIT(1);
            } else CP_WAIT(0);
            __syncthreads();
            mma_chunk(smA+(c&1)*(ACHB/2), smB, c*128, 8, mi, nig, lane, C);
            __syncthreads();
        }
        grid_barrier();

        // ===== Phase C: ctx chunk + pointwise =====
        { const char* src=(const char*)&g_ab[(size_t)(mt*5+4)*2*64*ASTRIDE];
          for(int i=tid;i<ACHB/16;i+=NTHR) cpa16(saA+i*16, src+(size_t)i*16);
          CP_COMMIT(); CP_WAIT(0); }
        __syncthreads();
        mma_chunk(smA, smB, 512, 2, mi, nig, lane, C);
        { int r=lane>>2, c4=lane&3;
          #pragma unroll
          for(int ni=0;ni<4;ni++){
              int col=nig*32+ni*8+c4*2;
              *(float2*)&gates[(mi*16+r)*68+col]  =make_float2(C[ni][0],C[ni][1]);
              *(float2*)&gates[(mi*16+r+8)*68+col]=make_float2(C[ni][2],C[ni][3]);
          } }
        __syncthreads();
        float swa=0.f, sfc=0.f;
        #pragma unroll
        for(int j=0;j<4;j++){
            int u=u0+j;
            float4 g4=*(float4*)&gates[prow*68+u*4];
            float gi=g4.x+bsum_s[u*4+0], gf=g4.y+bsum_s[u*4+1];
            float gg=g4.z+bsum_s[u*4+2], go=g4.w+bsum_s[u*4+3];
            float cn=sigm(gf)*cst[j]+sigm(gi)*tanhf(gg);
            float hn=sigm(go)*tanhf(cn);
            cst[j]=cn;
            swa+=hn*f1v[j]; sfc+=hn*w2v[j];
            ush hi,lo; bf16split(hn,hi,lo);
            int p4=pos4(u);
            g_ab[hHi+p4]=hi; g_ab[hLo+p4]=lo;
        }
        swa+=__shfl_xor_sync(0xffffffffu,swa,1); swa+=__shfl_xor_sync(0xffffffffu,swa,2);
        sfc+=__shfl_xor_sync(0xffffffffu,sfc,1); sfc+=__shfl_xor_sync(0xffffffffu,sfc,2);
        if((tid&3)==0){
            int b=mt*64+prow;
            g_wapart[b*32+nt]=swa;
            g_fcpart[((size_t)t*Bb+b)*32+nt]=sfc;
        }
        grid_barrier();
    }
}

__global__ void final_out(const float* __restrict__ x, const float* __restrict__ mask,
                          const float* __restrict__ w2, const float* __restrict__ b2,
                          float* __restrict__ out){
    __shared__ float w2s[Ff];
    if(threadIdx.x<Ff) w2s[threadIdx.x]=w2[512+threadIdx.x];
    __syncthreads();
    int gid=blockIdx.x*blockDim.x+threadIdx.x;
    int b=gid/Ll, l=gid%Ll;
    const float* fp=g_fcpart+(size_t)(l*Bb+b)*32;
    float s=0.f;
    #pragma unroll
    for(int j=0;j<32;j++) s+=fp[j];
    float m=mask[b*Ll+l];
    s*=m;
    const float* xr=x+(size_t)(b*Ll+l)*Ff;
    #pragma unroll 7
    for(int f=0;f<Ff;f++) s+=xr[f]*w2s[f];
    out[b*Ll+l]=(s+b2[0])*m;
}

extern "C" void kernel_launch(void* const* d_in, const int* in_sizes, int n_in,
                              void* d_out, int out_size){
    const float* x=(const float*)d_in[0];
    const float* mask=(const float*)d_in[1];
    const float* conv1w=(const float*)d_in[2];
    const float* conv1b=(const float*)d_in[3];
    const float* convw=(const float*)d_in[4];
    const float* convb=(const float*)d_in[5];
    const float* conv2w=(const float*)d_in[6];
    const float* conv2b=(const float*)d_in[7];
    const float* wih=(const float*)d_in[8];
    const float* whh=(const float*)d_in[9];
    const float* bih=(const float*)d_in[10];
    const float* bhh=(const float*)d_in[11];
    const float* fc1w=(const float*)d_in[12];
    const float* fc1b=(const float*)d_in[13];
    float* out=(float*)d_out;

    cudaFuncSetAttribute(scan, cudaFuncAttributeMaxDynamicSharedMemorySize, SMEM_SZ);
    pack_w<<<(32*64*544+255)/256, 256>>>(whh, wih);
    zero_ab<<<((int)(sizeof(g_ab)/16)+255)/256, 256>>>();
    prep<<<(Bb*Ll)/256, 256>>>(x, mask, conv1w, conv1b, convw, convb);
    scan<<<NBLK, NTHR, SMEM_SZ>>>(fc1w, fc1b, bih, bhh, conv2w);
    final_out<<<(Bb*Ll)/256, 256>>>(x, mask, conv2w, conv2b, out);
}